// round 2
// baseline (speedup 1.0000x reference)
#include <cuda_runtime.h>

#define NN    100000
#define EDGES 1600000
#define EE    (EDGES + NN)
#define F     128

// ---------------- device scratch (no allocation allowed) ----------------
__device__ float    g_hf[NN * F];   // per-layer transformed features h = X @ W
__device__ float    g_f0[NN * F];   // layer-1 output
__device__ float    g_f1[NN * F];   // layer-2 output
__device__ float    g_as[NN * 4];   // a_src per node per head
__device__ float    g_ad[NN * 4];   // a_dst per node per head
__device__ unsigned g_m[NN * 4];    // segment max (monotone-encoded float)
__device__ float    g_den[NN * 4];  // softmax denominator

// monotone float<->uint encoding so atomicMax works on signed floats.
// memset(0) is a valid "-inf" init: all finite encodings are > 0x00800000 > 0.
__device__ __forceinline__ unsigned encf(float f) {
    unsigned u = __float_as_uint(f);
    return (u & 0x80000000u) ? ~u : (u | 0x80000000u);
}
__device__ __forceinline__ float decf(unsigned u) {
    return (u & 0x80000000u) ? __uint_as_float(u & 0x7FFFFFFFu)
                             : __uint_as_float(~u);
}

// ---------------- GEMM (X@W) + fused attention-logit epilogue ----------------
// Block: 128 threads (one per output column), 32 rows per block.
// W chunk staged in smem, thread's W column chunk held in 32 registers.
__global__ __launch_bounds__(128) void gemm_attn(
    const float* __restrict__ fin, const float* __restrict__ W,
    const float* __restrict__ att_s, const float* __restrict__ att_d,
    float* __restrict__ hf, float* __restrict__ as_, float* __restrict__ ad_,
    int H)
{
    __shared__ float Ws[32 * F];     // 16 KB W chunk [k][col]
    __shared__ float xs[32][32];     // 4 KB  X chunk [row][k]
    __shared__ float ps_s[32][4];
    __shared__ float ps_d[32][4];

    const int t    = threadIdx.x;
    const int w    = t >> 5;
    const int lane = t & 31;
    const int row0 = blockIdx.x * 32;

    float acc[32];
#pragma unroll
    for (int r = 0; r < 32; r++) acc[r] = 0.f;

    for (int kc = 0; kc < 4; kc++) {
#pragma unroll
        for (int i = 0; i < 32; i++)
            Ws[i * F + t] = W[(kc * 32 + i) * F + t];
#pragma unroll
        for (int i = 0; i < 8; i++) {
            int idx = t + i * 128;          // 0..1023
            int r = idx >> 5, k = idx & 31;
            xs[r][k] = fin[(row0 + r) * F + kc * 32 + k];
        }
        __syncthreads();

        float wreg[32];
#pragma unroll
        for (int k = 0; k < 32; k++) wreg[k] = Ws[k * F + t];

        for (int r = 0; r < 32; r++) {
            const float4* xr = (const float4*)xs[r];
            float a = acc[r];
#pragma unroll
            for (int q = 0; q < 8; q++) {
                float4 xv = xr[q];
                a += xv.x * wreg[4 * q + 0];
                a += xv.y * wreg[4 * q + 1];
                a += xv.z * wreg[4 * q + 2];
                a += xv.w * wreg[4 * q + 3];
            }
            acc[r] = a;
        }
        __syncthreads();
    }

    const float vs = att_s[t], vd = att_d[t];
    for (int r = 0; r < 32; r++) {
        float v = acc[r];
        hf[(row0 + r) * F + t] = v;
        float ps = v * vs, pd = v * vd;
#pragma unroll
        for (int o = 16; o > 0; o >>= 1) {
            ps += __shfl_xor_sync(0xffffffffu, ps, o);
            pd += __shfl_xor_sync(0xffffffffu, pd, o);
        }
        if (lane == 0) { ps_s[r][w] = ps; ps_d[r][w] = pd; }
    }
    __syncthreads();

    if (H == 4) {
        int r = t >> 2, h = t & 3;   // heads align with warps (C=32)
        as_[(row0 + r) * 4 + h] = ps_s[r][h];
        ad_[(row0 + r) * 4 + h] = ps_d[r][h];
    } else if (t < 32) {
        as_[row0 + t] = ps_s[t][0] + ps_s[t][1] + ps_s[t][2] + ps_s[t][3];
        ad_[row0 + t] = ps_d[t][0] + ps_d[t][1] + ps_d[t][2] + ps_d[t][3];
    }
}

// ---------------- edge softmax passes ----------------
__device__ __forceinline__ void edge_sd(const int* __restrict__ ei, int e,
                                        int& s, int& d) {
    if (e < EDGES) { s = ei[e]; d = ei[EDGES + e]; }
    else           { s = d = e - EDGES; }       // self-loops
}

__global__ void edge_max(const int* __restrict__ ei,
                         const float* __restrict__ as_,
                         const float* __restrict__ ad_,
                         unsigned* __restrict__ m, int H)
{
    int e = blockIdx.x * blockDim.x + threadIdx.x;
    if (e >= EE) return;
    int s, d; edge_sd(ei, e, s, d);
    for (int h = 0; h < H; h++) {
        float v = as_[s * H + h] + ad_[d * H + h];
        v = v > 0.f ? v : 0.2f * v;             // leaky_relu(0.2)
        atomicMax(&m[d * H + h], encf(v));
    }
}

__global__ void edge_sum(const int* __restrict__ ei,
                         const float* __restrict__ as_,
                         const float* __restrict__ ad_,
                         const unsigned* __restrict__ m,
                         float* __restrict__ den, int H)
{
    int e = blockIdx.x * blockDim.x + threadIdx.x;
    if (e >= EE) return;
    int s, d; edge_sd(ei, e, s, d);
    for (int h = 0; h < H; h++) {
        float v = as_[s * H + h] + ad_[d * H + h];
        v = v > 0.f ? v : 0.2f * v;
        atomicAdd(&den[d * H + h], expf(v - decf(m[d * H + h])));
    }
}

// one warp per edge: lane handles 4 consecutive features (float4)
__global__ void edge_scatter(const int* __restrict__ ei,
                             const float* __restrict__ as_,
                             const float* __restrict__ ad_,
                             const unsigned* __restrict__ m,
                             const float* __restrict__ den,
                             const float* __restrict__ hf,
                             float* __restrict__ acc, int H)
{
    int g    = blockIdx.x * blockDim.x + threadIdx.x;
    int e    = g >> 5;
    int lane = g & 31;
    if (e >= EE) return;
    int s, d; edge_sd(ei, e, s, d);

    float alpha = 0.f;
    if (lane < H) {
        float v = as_[s * H + lane] + ad_[d * H + lane];
        v = v > 0.f ? v : 0.2f * v;
        alpha = expf(v - decf(m[d * H + lane])) / den[d * H + lane];
    }
    float4 hv = ((const float4*)hf)[s * 32 + lane];
    int   c0  = lane << 2;
    float a   = __shfl_sync(0xffffffffu, alpha, (H == 4) ? (c0 >> 5) : 0);

    float* o = acc + d * F + c0;
    atomicAdd(o + 0, a * hv.x);
    atomicAdd(o + 1, a * hv.y);
    atomicAdd(o + 2, a * hv.z);
    atomicAdd(o + 3, a * hv.w);
}

__global__ void finalize(float* __restrict__ acc, const float* __restrict__ b,
                         int elu)
{
    int i = blockIdx.x * blockDim.x + threadIdx.x;
    if (i >= NN * F) return;
    float v = acc[i] + b[i & 127];
    if (elu) v = v > 0.f ? v : (expf(v) - 1.f);
    acc[i] = v;
}

// ---------------- host side ----------------
static void run_layer(const float* fin, const float* W, const float* ss,
                      const float* dd, const float* bb, int H, float* acc,
                      int elu, const int* ei, float* hf, float* as_,
                      float* ad_, unsigned* m, float* den)
{
    gemm_attn<<<NN / 32, 128>>>(fin, W, ss, dd, hf, as_, ad_, H);
    cudaMemsetAsync(m,   0, (size_t)NN * H * sizeof(unsigned));
    cudaMemsetAsync(den, 0, (size_t)NN * H * sizeof(float));
    cudaMemsetAsync(acc, 0, (size_t)NN * F * sizeof(float));
    const int blk = 256;
    edge_max<<<(EE + blk - 1) / blk, blk>>>(ei, as_, ad_, m, H);
    edge_sum<<<(EE + blk - 1) / blk, blk>>>(ei, as_, ad_, m, den, H);
    long long tot = (long long)EE * 32;
    edge_scatter<<<(unsigned)((tot + blk - 1) / blk), blk>>>(ei, as_, ad_, m,
                                                             den, hf, acc, H);
    finalize<<<(NN * F + blk - 1) / blk, blk>>>(acc, bb, elu);
}

extern "C" void kernel_launch(void* const* d_in, const int* in_sizes, int n_in,
                              void* d_out, int out_size)
{
    const float* x  = (const float*)d_in[0];
    const int*   ei = (const int*)d_in[1];
    const float* W1 = (const float*)d_in[2];
    const float* s1 = (const float*)d_in[3];
    const float* d1 = (const float*)d_in[4];
    const float* b1 = (const float*)d_in[5];
    const float* W2 = (const float*)d_in[6];
    const float* s2 = (const float*)d_in[7];
    const float* d2 = (const float*)d_in[8];
    const float* b2 = (const float*)d_in[9];
    const float* W3 = (const float*)d_in[10];
    const float* s3 = (const float*)d_in[11];
    const float* d3 = (const float*)d_in[12];
    const float* b3 = (const float*)d_in[13];

    float *hf, *f0, *f1, *as_, *ad_, *den;
    unsigned* m;
    cudaGetSymbolAddress((void**)&hf,  g_hf);
    cudaGetSymbolAddress((void**)&f0,  g_f0);
    cudaGetSymbolAddress((void**)&f1,  g_f1);
    cudaGetSymbolAddress((void**)&as_, g_as);
    cudaGetSymbolAddress((void**)&ad_, g_ad);
    cudaGetSymbolAddress((void**)&m,   g_m);
    cudaGetSymbolAddress((void**)&den, g_den);

    run_layer(x,  W1, s1, d1, b1, 4, f0,             1, ei, hf, as_, ad_, m, den);
    run_layer(f0, W2, s2, d2, b2, 4, f1,             1, ei, hf, as_, ad_, m, den);
    run_layer(f1, W3, s3, d3, b3, 1, (float*)d_out,  0, ei, hf, as_, ad_, m, den);
}

// round 4
// speedup vs baseline: 2.1506x; 2.1506x over previous
#include <cuda_runtime.h>
#include <math_constants.h>

#define NN    100000
#define EDGES 1600000
#define EE    (EDGES + NN)
#define F     128

// ---------------- device scratch (no allocation allowed) ----------------
__device__ float g_hf[NN * F];   // per-layer transformed features h = X @ W
__device__ float g_f0[NN * F];   // layer-1 output
__device__ float g_f1[NN * F];   // layer-2 output
__device__ float g_as[NN * 4];   // a_src per node per head
__device__ float g_ad[NN * 4];   // a_dst per node per head
__device__ int   g_deg[NN];      // in-degree histogram
__device__ int   g_rs[NN + 1];   // CSR row starts (by dst)
__device__ int   g_cnt[NN];      // fill cursors
__device__ int   g_src[EE];      // CSR: src node per incoming edge

// ---------------- CSR build (by destination) ----------------
__global__ void csr_hist(const int* __restrict__ ei, int* __restrict__ deg)
{
    int e = blockIdx.x * blockDim.x + threadIdx.x;
    if (e >= EE) return;
    int d = (e < EDGES) ? ei[EDGES + e] : (e - EDGES);
    atomicAdd(&deg[d], 1);
}

// single-block exclusive scan over NN elements (few µs)
__global__ __launch_bounds__(1024) void csr_scan(const int* __restrict__ deg,
                                                 int* __restrict__ rs)
{
    __shared__ int sm[1024];
    __shared__ int carry;
    int t = threadIdx.x;
    if (t == 0) carry = 0;
    __syncthreads();
    for (int base = 0; base < NN; base += 1024) {
        int c = carry;
        int v = (base + t < NN) ? deg[base + t] : 0;
        sm[t] = v;
        __syncthreads();
#pragma unroll
        for (int o = 1; o < 1024; o <<= 1) {
            int x = (t >= o) ? sm[t - o] : 0;
            __syncthreads();
            sm[t] += x;
            __syncthreads();
        }
        if (base + t < NN) rs[base + t] = c + sm[t] - v;
        if (t == 0) carry = c + sm[1023];
        __syncthreads();
    }
    if (t == 0) rs[NN] = carry;
}

__global__ void csr_fill(const int* __restrict__ ei,
                         const int* __restrict__ rs,
                         int* __restrict__ cnt, int* __restrict__ csrc)
{
    int e = blockIdx.x * blockDim.x + threadIdx.x;
    if (e >= EE) return;
    int s, d;
    if (e < EDGES) { s = ei[e]; d = ei[EDGES + e]; }
    else           { s = d = e - EDGES; }
    int pos = rs[d] + atomicAdd(&cnt[d], 1);
    csrc[pos] = s;
}

// ---------------- GEMM (X@W) + fused attention-logit epilogue ----------------
__global__ __launch_bounds__(128) void gemm_attn(
    const float* __restrict__ fin, const float* __restrict__ W,
    const float* __restrict__ att_s, const float* __restrict__ att_d,
    float* __restrict__ hf, float* __restrict__ as_, float* __restrict__ ad_,
    int H)
{
    __shared__ float Ws[32 * F];
    __shared__ float xs[32][32];
    __shared__ float ps_s[32][4];
    __shared__ float ps_d[32][4];

    const int t    = threadIdx.x;
    const int w    = t >> 5;
    const int lane = t & 31;
    const int row0 = blockIdx.x * 32;

    float acc[32];
#pragma unroll
    for (int r = 0; r < 32; r++) acc[r] = 0.f;

    for (int kc = 0; kc < 4; kc++) {
#pragma unroll
        for (int i = 0; i < 32; i++)
            Ws[i * F + t] = W[(kc * 32 + i) * F + t];
#pragma unroll
        for (int i = 0; i < 8; i++) {
            int idx = t + i * 128;
            int r = idx >> 5, k = idx & 31;
            xs[r][k] = fin[(row0 + r) * F + kc * 32 + k];
        }
        __syncthreads();

        float wreg[32];
#pragma unroll
        for (int k = 0; k < 32; k++) wreg[k] = Ws[k * F + t];

        for (int r = 0; r < 32; r++) {
            const float4* xr = (const float4*)xs[r];
            float a = acc[r];
#pragma unroll
            for (int q = 0; q < 8; q++) {
                float4 xv = xr[q];
                a += xv.x * wreg[4 * q + 0];
                a += xv.y * wreg[4 * q + 1];
                a += xv.z * wreg[4 * q + 2];
                a += xv.w * wreg[4 * q + 3];
            }
            acc[r] = a;
        }
        __syncthreads();
    }

    const float vs = att_s[t], vd = att_d[t];
    for (int r = 0; r < 32; r++) {
        float v = acc[r];
        hf[(row0 + r) * F + t] = v;
        float ps = v * vs, pd = v * vd;
#pragma unroll
        for (int o = 16; o > 0; o >>= 1) {
            ps += __shfl_xor_sync(0xffffffffu, ps, o);
            pd += __shfl_xor_sync(0xffffffffu, pd, o);
        }
        if (lane == 0) { ps_s[r][w] = ps; ps_d[r][w] = pd; }
    }
    __syncthreads();

    if (H == 4) {
        int r = t >> 2, h = t & 3;
        as_[(row0 + r) * 4 + h] = ps_s[r][h];
        ad_[(row0 + r) * 4 + h] = ps_d[r][h];
    } else if (t < 32) {
        as_[row0 + t] = ps_s[t][0] + ps_s[t][1] + ps_s[t][2] + ps_s[t][3];
        ad_[row0 + t] = ps_d[t][0] + ps_d[t][1] + ps_d[t][2] + ps_d[t][3];
    }
}

// ---------------- fused softmax + aggregate: warp per dst node ----------------
// Lanes 0..H-1 own per-head online-softmax state (m, den); every lane
// accumulates 4 consecutive output channels (float4) in registers.
__global__ __launch_bounds__(256) void gat_gather(
    const int* __restrict__ rs, const int* __restrict__ csrc,
    const float* __restrict__ as_, const float* __restrict__ ad_,
    const float* __restrict__ hf, const float* __restrict__ b,
    float* __restrict__ out, int H, int elu)
{
    const int warp = (blockIdx.x * blockDim.x + threadIdx.x) >> 5;
    const int lane = threadIdx.x & 31;
    if (warp >= NN) return;
    const int d = warp;

    const int h = (H == 4) ? (lane >> 3) : 0;   // head owning this lane's channels

    float adv = 0.f;
    if (lane < H) adv = ad_[d * H + lane];

    float m = -CUDART_INF_F, den = 0.f;
    float4 acc = make_float4(0.f, 0.f, 0.f, 0.f);

    const int start = rs[d], end = rs[d + 1];
    const float4* __restrict__ hf4 = (const float4*)hf;

    for (int j = start; j < end; j += 32) {
        int sj = (j + lane < end) ? csrc[j + lane] : 0;
        int n  = min(32, end - j);
        for (int k = 0; k < n; k++) {
            int s = __shfl_sync(0xffffffffu, sj, k);
            float f = 1.f, p = 0.f;
            if (lane < H) {
                float v = as_[s * H + lane] + adv;
                v = v > 0.f ? v : 0.2f * v;            // leaky_relu(0.2)
                float mn = fmaxf(m, v);
                f = __expf(m - mn);                    // rescale (0 on first edge)
                p = __expf(v - mn);
                den = den * f + p;
                m = mn;
            }
            f = __shfl_sync(0xffffffffu, f, h);
            p = __shfl_sync(0xffffffffu, p, h);
            float4 hv = hf4[s * 32 + lane];
            acc.x = acc.x * f + p * hv.x;
            acc.y = acc.y * f + p * hv.y;
            acc.z = acc.z * f + p * hv.z;
            acc.w = acc.w * f + p * hv.w;
        }
    }

    float dh  = __shfl_sync(0xffffffffu, den, h);
    float inv = 1.f / dh;
    const float4 bv = ((const float4*)b)[lane];
    float4 o;
    o.x = acc.x * inv + bv.x;
    o.y = acc.y * inv + bv.y;
    o.z = acc.z * inv + bv.z;
    o.w = acc.w * inv + bv.w;
    if (elu) {
        o.x = o.x > 0.f ? o.x : (__expf(o.x) - 1.f);
        o.y = o.y > 0.f ? o.y : (__expf(o.y) - 1.f);
        o.z = o.z > 0.f ? o.z : (__expf(o.z) - 1.f);
        o.w = o.w > 0.f ? o.w : (__expf(o.w) - 1.f);
    }
    ((float4*)out)[d * 32 + lane] = o;
}

// ---------------- host side ----------------
static void run_layer(const float* fin, const float* W, const float* ss,
                      const float* dd, const float* bb, int H, float* outp,
                      int elu, float* hf, float* as_, float* ad_,
                      const int* rs, const int* csrc)
{
    gemm_attn<<<NN / 32, 128>>>(fin, W, ss, dd, hf, as_, ad_, H);
    // 8 warps/block, warp per dst node
    gat_gather<<<(NN + 7) / 8, 256>>>(rs, csrc, as_, ad_, hf, bb, outp, H, elu);
}

extern "C" void kernel_launch(void* const* d_in, const int* in_sizes, int n_in,
                              void* d_out, int out_size)
{
    const float* x  = (const float*)d_in[0];
    const int*   ei = (const int*)d_in[1];
    const float* W1 = (const float*)d_in[2];
    const float* s1 = (const float*)d_in[3];
    const float* d1 = (const float*)d_in[4];
    const float* b1 = (const float*)d_in[5];
    const float* W2 = (const float*)d_in[6];
    const float* s2 = (const float*)d_in[7];
    const float* d2 = (const float*)d_in[8];
    const float* b2 = (const float*)d_in[9];
    const float* W3 = (const float*)d_in[10];
    const float* s3 = (const float*)d_in[11];
    const float* d3 = (const float*)d_in[12];
    const float* b3 = (const float*)d_in[13];

    float *hf, *f0, *f1, *as_, *ad_;
    int *deg, *rs, *cnt, *csrc;
    cudaGetSymbolAddress((void**)&hf,   g_hf);
    cudaGetSymbolAddress((void**)&f0,   g_f0);
    cudaGetSymbolAddress((void**)&f1,   g_f1);
    cudaGetSymbolAddress((void**)&as_,  g_as);
    cudaGetSymbolAddress((void**)&ad_,  g_ad);
    cudaGetSymbolAddress((void**)&deg,  g_deg);
    cudaGetSymbolAddress((void**)&rs,   g_rs);
    cudaGetSymbolAddress((void**)&cnt,  g_cnt);
    cudaGetSymbolAddress((void**)&csrc, g_src);

    // ---- build dst-CSR once per launch (graph is static across layers) ----
    cudaMemsetAsync(deg, 0, NN * sizeof(int));
    cudaMemsetAsync(cnt, 0, NN * sizeof(int));
    const int blk = 256;
    csr_hist<<<(EE + blk - 1) / blk, blk>>>(ei, deg);
    csr_scan<<<1, 1024>>>(deg, rs);
    csr_fill<<<(EE + blk - 1) / blk, blk>>>(ei, rs, cnt, csrc);

    run_layer(x,  W1, s1, d1, b1, 4, f0,            1, hf, as_, ad_, rs, csrc);
    run_layer(f0, W2, s2, d2, b2, 4, f1,            1, hf, as_, ad_, rs, csrc);
    run_layer(f1, W3, s3, d3, b3, 1, (float*)d_out, 0, hf, as_, ad_, rs, csrc);
}

// round 5
// speedup vs baseline: 2.5479x; 1.1847x over previous
#include <cuda_runtime.h>
#include <math_constants.h>

#define NN    100000
#define EDGES 1600000
#define EE    (EDGES + NN)
#define F     128

// ---------------- device scratch (no allocation allowed) ----------------
__device__ float g_hf[NN * F];
__device__ float g_f0[NN * F];
__device__ float g_f1[NN * F];
__device__ float g_as[NN * 4];
__device__ float g_ad[NN * 4];
__device__ int   g_deg[NN];
__device__ int   g_rs[NN + 1];
__device__ int   g_cnt[NN];
__device__ int   g_src[EE];

// ---------------- CSR build (by destination) ----------------
__global__ void csr_hist(const int* __restrict__ ei, int* __restrict__ deg)
{
    int e = blockIdx.x * blockDim.x + threadIdx.x;
    if (e >= EE) return;
    int d = (e < EDGES) ? ei[EDGES + e] : (e - EDGES);
    atomicAdd(&deg[d], 1);
}

__global__ __launch_bounds__(1024) void csr_scan(const int* __restrict__ deg,
                                                 int* __restrict__ rs)
{
    __shared__ int sm[1024];
    __shared__ int carry;
    int t = threadIdx.x;
    if (t == 0) carry = 0;
    __syncthreads();
    for (int base = 0; base < NN; base += 1024) {
        int c = carry;
        int v = (base + t < NN) ? deg[base + t] : 0;
        sm[t] = v;
        __syncthreads();
#pragma unroll
        for (int o = 1; o < 1024; o <<= 1) {
            int x = (t >= o) ? sm[t - o] : 0;
            __syncthreads();
            sm[t] += x;
            __syncthreads();
        }
        if (base + t < NN) rs[base + t] = c + sm[t] - v;
        if (t == 0) carry = c + sm[1023];
        __syncthreads();
    }
    if (t == 0) rs[NN] = carry;
}

__global__ void csr_fill(const int* __restrict__ ei,
                         const int* __restrict__ rs,
                         int* __restrict__ cnt, int* __restrict__ csrc)
{
    int e = blockIdx.x * blockDim.x + threadIdx.x;
    if (e >= EE) return;
    int s, d;
    if (e < EDGES) { s = ei[e]; d = ei[EDGES + e]; }
    else           { s = d = e - EDGES; }
    int pos = rs[d] + atomicAdd(&cnt[d], 1);
    csrc[pos] = s;
}

// ---------------- GEMM (X@W) + fused attention-logit epilogue ----------------
__global__ __launch_bounds__(128) void gemm_attn(
    const float* __restrict__ fin, const float* __restrict__ W,
    const float* __restrict__ att_s, const float* __restrict__ att_d,
    float* __restrict__ hf, float* __restrict__ as_, float* __restrict__ ad_,
    int H)
{
    __shared__ float Ws[32 * F];
    __shared__ float xs[32][32];
    __shared__ float ps_s[32][4];
    __shared__ float ps_d[32][4];

    const int t    = threadIdx.x;
    const int w    = t >> 5;
    const int lane = t & 31;
    const int row0 = blockIdx.x * 32;

    float acc[32];
#pragma unroll
    for (int r = 0; r < 32; r++) acc[r] = 0.f;

    for (int kc = 0; kc < 4; kc++) {
#pragma unroll
        for (int i = 0; i < 32; i++)
            Ws[i * F + t] = W[(kc * 32 + i) * F + t];
#pragma unroll
        for (int i = 0; i < 8; i++) {
            int idx = t + i * 128;
            int r = idx >> 5, k = idx & 31;
            xs[r][k] = fin[(row0 + r) * F + kc * 32 + k];
        }
        __syncthreads();

        float wreg[32];
#pragma unroll
        for (int k = 0; k < 32; k++) wreg[k] = Ws[k * F + t];

        // 2 independent partial sums per row + row-unroll 4 -> 8 live FFMA chains
#pragma unroll 4
        for (int r = 0; r < 32; r++) {
            const float4* xr = (const float4*)xs[r];
            float a0 = 0.f, a1 = 0.f;
#pragma unroll
            for (int q = 0; q < 8; q += 2) {
                float4 xv = xr[q];
                float4 xw = xr[q + 1];
                a0 += xv.x * wreg[4 * q + 0];
                a0 += xv.y * wreg[4 * q + 1];
                a0 += xv.z * wreg[4 * q + 2];
                a0 += xv.w * wreg[4 * q + 3];
                a1 += xw.x * wreg[4 * q + 4];
                a1 += xw.y * wreg[4 * q + 5];
                a1 += xw.z * wreg[4 * q + 6];
                a1 += xw.w * wreg[4 * q + 7];
            }
            acc[r] += a0 + a1;
        }
        __syncthreads();
    }

    const float vs = att_s[t], vd = att_d[t];
    for (int r = 0; r < 32; r++) {
        float v = acc[r];
        hf[(row0 + r) * F + t] = v;
        float ps = v * vs, pd = v * vd;
#pragma unroll
        for (int o = 16; o > 0; o >>= 1) {
            ps += __shfl_xor_sync(0xffffffffu, ps, o);
            pd += __shfl_xor_sync(0xffffffffu, pd, o);
        }
        if (lane == 0) { ps_s[r][w] = ps; ps_d[r][w] = pd; }
    }
    __syncthreads();

    if (H == 4) {
        int r = t >> 2, h = t & 3;
        as_[(row0 + r) * 4 + h] = ps_s[r][h];
        ad_[(row0 + r) * 4 + h] = ps_d[r][h];
    } else if (t < 32) {
        as_[row0 + t] = ps_s[t][0] + ps_s[t][1] + ps_s[t][2] + ps_s[t][3];
        ad_[row0 + t] = ps_d[t][0] + ps_d[t][1] + ps_d[t][2] + ps_d[t][3];
    }
}

// ---------------- fused softmax + aggregate: warp per dst node ----------------
// Edges processed in blocks of 8. Lane owns (edge = lane&7, head = lane>>3):
// logits computed in parallel, 8-lane butterfly reductions give block max/sum,
// online rescale happens once per 8-edge block. The lane->head map (lane>>3)
// equals the head of the lane's 4 output channels, so f/den apply in-place.
__global__ __launch_bounds__(256) void gat_gather(
    const int* __restrict__ rs, const int* __restrict__ csrc,
    const float* __restrict__ as_, const float* __restrict__ ad_,
    const float* __restrict__ hf, const float* __restrict__ b,
    float* __restrict__ out, int H, int elu)
{
    const int warp = (blockIdx.x * blockDim.x + threadIdx.x) >> 5;
    const int lane = threadIdx.x & 31;
    if (warp >= NN) return;
    const int d = warp;

    const int h = (H == 4) ? (lane >> 3) : 0;   // head of this lane's channels
    const float adv = ad_[d * H + h];

    float m = -CUDART_INF_F, den = 0.f;
    float4 acc = make_float4(0.f, 0.f, 0.f, 0.f);

    const int start = rs[d], end = rs[d + 1];
    const float4* __restrict__ hf4 = (const float4*)hf;
    const int gbase = lane & 24;                // 8-lane group base for p shuffle

    for (int j = start; j < end; j += 32) {
        int sj = (j + lane < end) ? csrc[j + lane] : 0;
        int nb = min(32, end - j);
        for (int base = 0; base < nb; base += 8) {
            int nk = min(8, nb - base);
            // --- parallel logits: my edge = base + (lane&7), my head = h ---
            int  s_my  = __shfl_sync(0xffffffffu, sj, base + (lane & 7));
            bool valid = (lane & 7) < nk;
            float v = -CUDART_INF_F;
            if (valid) {
                float vv = as_[s_my * H + h] + adv;
                v = vv > 0.f ? vv : 0.2f * vv;       // leaky_relu(0.2)
            }
            // block max within 8-lane head group
            float bm = v;
            bm = fmaxf(bm, __shfl_xor_sync(0xffffffffu, bm, 1));
            bm = fmaxf(bm, __shfl_xor_sync(0xffffffffu, bm, 2));
            bm = fmaxf(bm, __shfl_xor_sync(0xffffffffu, bm, 4));
            float mn = fmaxf(m, bm);
            float f  = __expf(m - mn);               // 0 on first block
            float p  = valid ? __expf(v - mn) : 0.f;
            float ps = p;
            ps += __shfl_xor_sync(0xffffffffu, ps, 1);
            ps += __shfl_xor_sync(0xffffffffu, ps, 2);
            ps += __shfl_xor_sync(0xffffffffu, ps, 4);
            den = den * f + ps;
            m = mn;
            acc.x *= f; acc.y *= f; acc.z *= f; acc.w *= f;
            // --- aggregation: no cross-edge serial dependency except acc FMA ---
            for (int k = 0; k < nk; k++) {
                int   s  = __shfl_sync(0xffffffffu, sj, base + k);
                float pk = __shfl_sync(0xffffffffu, p, gbase + k);
                float4 hv = hf4[s * 32 + lane];
                acc.x += pk * hv.x;
                acc.y += pk * hv.y;
                acc.z += pk * hv.z;
                acc.w += pk * hv.w;
            }
        }
    }

    float inv = 1.f / den;                           // den already per-head-correct
    const float4 bv = ((const float4*)b)[lane];
    float4 o;
    o.x = acc.x * inv + bv.x;
    o.y = acc.y * inv + bv.y;
    o.z = acc.z * inv + bv.z;
    o.w = acc.w * inv + bv.w;
    if (elu) {
        o.x = o.x > 0.f ? o.x : (__expf(o.x) - 1.f);
        o.y = o.y > 0.f ? o.y : (__expf(o.y) - 1.f);
        o.z = o.z > 0.f ? o.z : (__expf(o.z) - 1.f);
        o.w = o.w > 0.f ? o.w : (__expf(o.w) - 1.f);
    }
    ((float4*)out)[d * 32 + lane] = o;
}

// ---------------- host side ----------------
static void run_layer(const float* fin, const float* W, const float* ss,
                      const float* dd, const float* bb, int H, float* outp,
                      int elu, float* hf, float* as_, float* ad_,
                      const int* rs, const int* csrc)
{
    gemm_attn<<<NN / 32, 128>>>(fin, W, ss, dd, hf, as_, ad_, H);
    gat_gather<<<(NN + 7) / 8, 256>>>(rs, csrc, as_, ad_, hf, bb, outp, H, elu);
}

extern "C" void kernel_launch(void* const* d_in, const int* in_sizes, int n_in,
                              void* d_out, int out_size)
{
    const float* x  = (const float*)d_in[0];
    const int*   ei = (const int*)d_in[1];
    const float* W1 = (const float*)d_in[2];
    const float* s1 = (const float*)d_in[3];
    const float* d1 = (const float*)d_in[4];
    const float* b1 = (const float*)d_in[5];
    const float* W2 = (const float*)d_in[6];
    const float* s2 = (const float*)d_in[7];
    const float* d2 = (const float*)d_in[8];
    const float* b2 = (const float*)d_in[9];
    const float* W3 = (const float*)d_in[10];
    const float* s3 = (const float*)d_in[11];
    const float* d3 = (const float*)d_in[12];
    const float* b3 = (const float*)d_in[13];

    float *hf, *f0, *f1, *as_, *ad_;
    int *deg, *rs, *cnt, *csrc;
    cudaGetSymbolAddress((void**)&hf,   g_hf);
    cudaGetSymbolAddress((void**)&f0,   g_f0);
    cudaGetSymbolAddress((void**)&f1,   g_f1);
    cudaGetSymbolAddress((void**)&as_,  g_as);
    cudaGetSymbolAddress((void**)&ad_,  g_ad);
    cudaGetSymbolAddress((void**)&deg,  g_deg);
    cudaGetSymbolAddress((void**)&rs,   g_rs);
    cudaGetSymbolAddress((void**)&cnt,  g_cnt);
    cudaGetSymbolAddress((void**)&csrc, g_src);

    cudaMemsetAsync(deg, 0, NN * sizeof(int));
    cudaMemsetAsync(cnt, 0, NN * sizeof(int));
    const int blk = 256;
    csr_hist<<<(EE + blk - 1) / blk, blk>>>(ei, deg);
    csr_scan<<<1, 1024>>>(deg, rs);
    csr_fill<<<(EE + blk - 1) / blk, blk>>>(ei, rs, cnt, csrc);

    run_layer(x,  W1, s1, d1, b1, 4, f0,            1, hf, as_, ad_, rs, csrc);
    run_layer(f0, W2, s2, d2, b2, 4, f1,            1, hf, as_, ad_, rs, csrc);
    run_layer(f1, W3, s3, d3, b3, 1, (float*)d_out, 0, hf, as_, ad_, rs, csrc);
}

// round 6
// speedup vs baseline: 3.4831x; 1.3670x over previous
#include <cuda_runtime.h>
#include <math_constants.h>

#define NN    100000
#define EDGES 1600000
#define EE    (EDGES + NN)
#define F     128

// ---------------- device scratch (no allocation allowed) ----------------
__device__ float g_hf[NN * F];
__device__ float g_f0[NN * F];
__device__ float g_f1[NN * F];
__device__ float g_as[NN * 4];
__device__ float g_ad[NN * 4];
__device__ int   g_deg[NN];
__device__ int   g_rs[NN + 1];
__device__ int   g_cnt[NN];
__device__ int   g_src[EE];

// ---------------- CSR build (by destination) ----------------
__global__ void csr_hist(const int* __restrict__ ei, int* __restrict__ deg)
{
    int e = blockIdx.x * blockDim.x + threadIdx.x;
    if (e >= EE) return;
    int d = (e < EDGES) ? ei[EDGES + e] : (e - EDGES);
    atomicAdd(&deg[d], 1);
}

// single-block scan: thread-serial chunks + warp-shuffle block scan
__global__ __launch_bounds__(1024) void csr_scan(const int* __restrict__ deg,
                                                 int* __restrict__ rs)
{
    __shared__ int wsum[32];
    const int t    = threadIdx.x;
    const int lane = t & 31;
    const int w    = t >> 5;
    const int CH   = (NN + 1023) / 1024;       // 98
    const int lo   = t * CH;
    const int hi   = min(lo + CH, NN);

    int sum = 0;
    for (int i = lo; i < hi; i++) sum += deg[i];

    int inc = sum;
#pragma unroll
    for (int o = 1; o < 32; o <<= 1) {
        int x = __shfl_up_sync(0xffffffffu, inc, o);
        if (lane >= o) inc += x;
    }
    if (lane == 31) wsum[w] = inc;
    __syncthreads();
    if (w == 0) {
        int v = wsum[lane];
        int s = v;
#pragma unroll
        for (int o = 1; o < 32; o <<= 1) {
            int x = __shfl_up_sync(0xffffffffu, s, o);
            if (lane >= o) s += x;
        }
        wsum[lane] = s - v;                    // exclusive warp offsets
    }
    __syncthreads();

    int run = wsum[w] + inc - sum;             // exclusive prefix for this thread
    for (int i = lo; i < hi; i++) { rs[i] = run; run += deg[i]; }
    if (t == 1023) rs[NN] = run;
}

__global__ void csr_fill(const int* __restrict__ ei,
                         const int* __restrict__ rs,
                         int* __restrict__ cnt, int* __restrict__ csrc)
{
    int e = blockIdx.x * blockDim.x + threadIdx.x;
    if (e >= EE) return;
    int s, d;
    if (e < EDGES) { s = ei[e]; d = ei[EDGES + e]; }
    else           { s = d = e - EDGES; }
    int pos = rs[d] + atomicAdd(&cnt[d], 1);
    csrc[pos] = s;
}

// ---------------- register-tiled GEMM + fused attention-logit epilogue -------
// BM=64 rows, BN=128 (full), 256 threads; thread tile mr=4 x nr=8 (2x float4).
__global__ __launch_bounds__(256) void gemm_attn(
    const float* __restrict__ fin, const float* __restrict__ W,
    const float* __restrict__ att_s, const float* __restrict__ att_d,
    float* __restrict__ hf, float* __restrict__ as_, float* __restrict__ ad_,
    int H)
{
    __shared__ float  Xs[64][33];      // [row][k], pad 33 -> conflict-free
    __shared__ float4 Ws4[32 * 32];    // [k][col/4], 512B per k row

    const int t    = threadIdx.x;
    const int lane = t & 31;
    const int tcol = t & 15;           // column group (nr=8: cols tcol*4, 64+tcol*4)
    const int trow = t >> 4;           // row group (rows trow*4 .. +3)
    const int row0 = blockIdx.x * 64;

    float acc[4][8];
#pragma unroll
    for (int i = 0; i < 4; i++)
#pragma unroll
        for (int j = 0; j < 8; j++) acc[i][j] = 0.f;

    for (int kc = 0; kc < 4; kc++) {
        // X chunk: 64 rows x 32 k  (2 float4 per thread, coalesced)
#pragma unroll
        for (int i = 0; i < 2; i++) {
            int idx = t + 256 * i;                 // 0..511
            int r = idx >> 3, c = idx & 7;
            int gr = min(row0 + r, NN - 1);
            float4 v = *(const float4*)&fin[gr * F + kc * 32 + 4 * c];
            Xs[r][4 * c + 0] = v.x;
            Xs[r][4 * c + 1] = v.y;
            Xs[r][4 * c + 2] = v.z;
            Xs[r][4 * c + 3] = v.w;
        }
        // W chunk: 32 k x 128 cols (4 float4 per thread, coalesced)
#pragma unroll
        for (int i = 0; i < 4; i++) {
            int idx = t + 256 * i;                 // 0..1023
            int k = idx >> 5, c = idx & 31;
            Ws4[k * 32 + c] = *(const float4*)&W[(kc * 32 + k) * F + 4 * c];
        }
        __syncthreads();

#pragma unroll
        for (int k = 0; k < 32; k++) {
            float a0 = Xs[trow * 4 + 0][k];
            float a1 = Xs[trow * 4 + 1][k];
            float a2 = Xs[trow * 4 + 2][k];
            float a3 = Xs[trow * 4 + 3][k];
            float4 b0 = Ws4[k * 32 + tcol];
            float4 b1 = Ws4[k * 32 + 16 + tcol];
            acc[0][0] += a0 * b0.x; acc[0][1] += a0 * b0.y;
            acc[0][2] += a0 * b0.z; acc[0][3] += a0 * b0.w;
            acc[0][4] += a0 * b1.x; acc[0][5] += a0 * b1.y;
            acc[0][6] += a0 * b1.z; acc[0][7] += a0 * b1.w;
            acc[1][0] += a1 * b0.x; acc[1][1] += a1 * b0.y;
            acc[1][2] += a1 * b0.z; acc[1][3] += a1 * b0.w;
            acc[1][4] += a1 * b1.x; acc[1][5] += a1 * b1.y;
            acc[1][6] += a1 * b1.z; acc[1][7] += a1 * b1.w;
            acc[2][0] += a2 * b0.x; acc[2][1] += a2 * b0.y;
            acc[2][2] += a2 * b0.z; acc[2][3] += a2 * b0.w;
            acc[2][4] += a2 * b1.x; acc[2][5] += a2 * b1.y;
            acc[2][6] += a2 * b1.z; acc[2][7] += a2 * b1.w;
            acc[3][0] += a3 * b0.x; acc[3][1] += a3 * b0.y;
            acc[3][2] += a3 * b0.z; acc[3][3] += a3 * b0.w;
            acc[3][4] += a3 * b1.x; acc[3][5] += a3 * b1.y;
            acc[3][6] += a3 * b1.z; acc[3][7] += a3 * b1.w;
        }
        __syncthreads();
    }

    // attention vectors for this thread's columns
    const float4 sA = ((const float4*)att_s)[tcol];
    const float4 sB = ((const float4*)att_s)[16 + tcol];
    const float4 dA = ((const float4*)att_d)[tcol];
    const float4 dB = ((const float4*)att_d)[16 + tcol];

#pragma unroll
    for (int i = 0; i < 4; i++) {
        int gr = row0 + trow * 4 + i;
        bool ok = gr < NN;
        if (ok) {
            float4 oA = make_float4(acc[i][0], acc[i][1], acc[i][2], acc[i][3]);
            float4 oB = make_float4(acc[i][4], acc[i][5], acc[i][6], acc[i][7]);
            *(float4*)&hf[gr * F + tcol * 4]      = oA;
            *(float4*)&hf[gr * F + 64 + tcol * 4] = oB;
        }
        float psA = acc[i][0] * sA.x + acc[i][1] * sA.y + acc[i][2] * sA.z + acc[i][3] * sA.w;
        float psB = acc[i][4] * sB.x + acc[i][5] * sB.y + acc[i][6] * sB.z + acc[i][7] * sB.w;
        float pdA = acc[i][0] * dA.x + acc[i][1] * dA.y + acc[i][2] * dA.z + acc[i][3] * dA.w;
        float pdB = acc[i][4] * dB.x + acc[i][5] * dB.y + acc[i][6] * dB.z + acc[i][7] * dB.w;
        if (H == 4) {
            // 8-lane groups share (trow, head): cols 0..31 -> head tcol>>3
#pragma unroll
            for (int o = 1; o < 8; o <<= 1) {
                psA += __shfl_xor_sync(0xffffffffu, psA, o);
                psB += __shfl_xor_sync(0xffffffffu, psB, o);
                pdA += __shfl_xor_sync(0xffffffffu, pdA, o);
                pdB += __shfl_xor_sync(0xffffffffu, pdB, o);
            }
            if ((lane & 7) == 0 && ok) {
                int h0 = (lane >> 3) & 1;           // == tcol>>3
                as_[gr * 4 + h0]     = psA;
                as_[gr * 4 + h0 + 2] = psB;
                ad_[gr * 4 + h0]     = pdA;
                ad_[gr * 4 + h0 + 2] = pdB;
            }
        } else {
            float s = psA + psB, dd = pdA + pdB;
#pragma unroll
            for (int o = 1; o < 16; o <<= 1) {
                s  += __shfl_xor_sync(0xffffffffu, s,  o);
                dd += __shfl_xor_sync(0xffffffffu, dd, o);
            }
            if ((lane & 15) == 0 && ok) { as_[gr] = s; ad_[gr] = dd; }
        }
    }
}

// ---------------- fused softmax + aggregate: warp per dst node ----------------
__global__ __launch_bounds__(256) void gat_gather(
    const int* __restrict__ rs, const int* __restrict__ csrc,
    const float* __restrict__ as_, const float* __restrict__ ad_,
    const float* __restrict__ hf, const float* __restrict__ b,
    float* __restrict__ out, int H, int elu)
{
    const int warp = (blockIdx.x * blockDim.x + threadIdx.x) >> 5;
    const int lane = threadIdx.x & 31;
    if (warp >= NN) return;
    const int d = warp;

    const int h = (H == 4) ? (lane >> 3) : 0;
    const float adv = ad_[d * H + h];

    float m = -CUDART_INF_F, den = 0.f;
    float4 acc = make_float4(0.f, 0.f, 0.f, 0.f);

    const int start = rs[d], end = rs[d + 1];
    const float4* __restrict__ hf4 = (const float4*)hf;
    const int gbase = lane & 24;

    for (int j = start; j < end; j += 32) {
        int sj = (j + lane < end) ? csrc[j + lane] : 0;
        int nb = min(32, end - j);
        for (int base = 0; base < nb; base += 8) {
            int nk = min(8, nb - base);
            int  s_my  = __shfl_sync(0xffffffffu, sj, base + (lane & 7));
            bool valid = (lane & 7) < nk;
            float v = -CUDART_INF_F;
            if (valid) {
                float vv = as_[s_my * H + h] + adv;
                v = vv > 0.f ? vv : 0.2f * vv;
            }
            float bm = v;
            bm = fmaxf(bm, __shfl_xor_sync(0xffffffffu, bm, 1));
            bm = fmaxf(bm, __shfl_xor_sync(0xffffffffu, bm, 2));
            bm = fmaxf(bm, __shfl_xor_sync(0xffffffffu, bm, 4));
            float mn = fmaxf(m, bm);
            float f  = __expf(m - mn);
            float p  = valid ? __expf(v - mn) : 0.f;
            float ps = p;
            ps += __shfl_xor_sync(0xffffffffu, ps, 1);
            ps += __shfl_xor_sync(0xffffffffu, ps, 2);
            ps += __shfl_xor_sync(0xffffffffu, ps, 4);
            den = den * f + ps;
            m = mn;
            acc.x *= f; acc.y *= f; acc.z *= f; acc.w *= f;
            for (int k = 0; k < nk; k++) {
                int   s  = __shfl_sync(0xffffffffu, sj, base + k);
                float pk = __shfl_sync(0xffffffffu, p, gbase + k);
                float4 hv = hf4[s * 32 + lane];
                acc.x += pk * hv.x;
                acc.y += pk * hv.y;
                acc.z += pk * hv.z;
                acc.w += pk * hv.w;
            }
        }
    }

    float inv = 1.f / den;
    const float4 bv = ((const float4*)b)[lane];
    float4 o;
    o.x = acc.x * inv + bv.x;
    o.y = acc.y * inv + bv.y;
    o.z = acc.z * inv + bv.z;
    o.w = acc.w * inv + bv.w;
    if (elu) {
        o.x = o.x > 0.f ? o.x : (__expf(o.x) - 1.f);
        o.y = o.y > 0.f ? o.y : (__expf(o.y) - 1.f);
        o.z = o.z > 0.f ? o.z : (__expf(o.z) - 1.f);
        o.w = o.w > 0.f ? o.w : (__expf(o.w) - 1.f);
    }
    ((float4*)out)[d * 32 + lane] = o;
}

// ---------------- host side ----------------
static void run_layer(const float* fin, const float* W, const float* ss,
                      const float* dd, const float* bb, int H, float* outp,
                      int elu, float* hf, float* as_, float* ad_,
                      const int* rs, const int* csrc)
{
    gemm_attn<<<(NN + 63) / 64, 256>>>(fin, W, ss, dd, hf, as_, ad_, H);
    gat_gather<<<(NN + 7) / 8, 256>>>(rs, csrc, as_, ad_, hf, bb, outp, H, elu);
}

extern "C" void kernel_launch(void* const* d_in, const int* in_sizes, int n_in,
                              void* d_out, int out_size)
{
    const float* x  = (const float*)d_in[0];
    const int*   ei = (const int*)d_in[1];
    const float* W1 = (const float*)d_in[2];
    const float* s1 = (const float*)d_in[3];
    const float* d1 = (const float*)d_in[4];
    const float* b1 = (const float*)d_in[5];
    const float* W2 = (const float*)d_in[6];
    const float* s2 = (const float*)d_in[7];
    const float* d2 = (const float*)d_in[8];
    const float* b2 = (const float*)d_in[9];
    const float* W3 = (const float*)d_in[10];
    const float* s3 = (const float*)d_in[11];
    const float* d3 = (const float*)d_in[12];
    const float* b3 = (const float*)d_in[13];

    float *hf, *f0, *f1, *as_, *ad_;
    int *deg, *rs, *cnt, *csrc;
    cudaGetSymbolAddress((void**)&hf,   g_hf);
    cudaGetSymbolAddress((void**)&f0,   g_f0);
    cudaGetSymbolAddress((void**)&f1,   g_f1);
    cudaGetSymbolAddress((void**)&as_,  g_as);
    cudaGetSymbolAddress((void**)&ad_,  g_ad);
    cudaGetSymbolAddress((void**)&deg,  g_deg);
    cudaGetSymbolAddress((void**)&rs,   g_rs);
    cudaGetSymbolAddress((void**)&cnt,  g_cnt);
    cudaGetSymbolAddress((void**)&csrc, g_src);

    cudaMemsetAsync(deg, 0, NN * sizeof(int));
    cudaMemsetAsync(cnt, 0, NN * sizeof(int));
    const int blk = 256;
    csr_hist<<<(EE + blk - 1) / blk, blk>>>(ei, deg);
    csr_scan<<<1, 1024>>>(deg, rs);
    csr_fill<<<(EE + blk - 1) / blk, blk>>>(ei, rs, cnt, csrc);

    run_layer(x,  W1, s1, d1, b1, 4, f0,            1, hf, as_, ad_, rs, csrc);
    run_layer(f0, W2, s2, d2, b2, 4, f1,            1, hf, as_, ad_, rs, csrc);
    run_layer(f1, W3, s3, d3, b3, 1, (float*)d_out, 0, hf, as_, ad_, rs, csrc);
}

// round 7
// speedup vs baseline: 3.5396x; 1.0162x over previous
#include <cuda_runtime.h>
#include <cuda_fp16.h>
#include <math_constants.h>

#define NN    100000
#define EDGES 1600000
#define EE    (EDGES + NN)
#define F     128

// ---------------- device scratch (no allocation allowed) ----------------
__device__ uint2 g_hf[NN * 32];  // h = X@W in fp16 (128 halves = 32 uint2/node)
__device__ float g_f0[NN * F];
__device__ float g_f1[NN * F];
__device__ float g_as[NN * 4];
__device__ float g_ad[NN * 4];
__device__ int   g_deg[NN];
__device__ int   g_rs[NN + 1];
__device__ int   g_cnt[NN];
__device__ int   g_src[EE];

// ---------------- CSR build (by destination) ----------------
__global__ void csr_hist(const int* __restrict__ ei, int* __restrict__ deg)
{
    int e = blockIdx.x * blockDim.x + threadIdx.x;
    if (e >= EE) return;
    int d = (e < EDGES) ? ei[EDGES + e] : (e - EDGES);
    atomicAdd(&deg[d], 1);
}

__global__ __launch_bounds__(1024) void csr_scan(const int* __restrict__ deg,
                                                 int* __restrict__ rs)
{
    __shared__ int wsum[32];
    const int t    = threadIdx.x;
    const int lane = t & 31;
    const int w    = t >> 5;
    const int CH   = (NN + 1023) / 1024;
    const int lo   = t * CH;
    const int hi   = min(lo + CH, NN);

    int sum = 0;
    for (int i = lo; i < hi; i++) sum += deg[i];

    int inc = sum;
#pragma unroll
    for (int o = 1; o < 32; o <<= 1) {
        int x = __shfl_up_sync(0xffffffffu, inc, o);
        if (lane >= o) inc += x;
    }
    if (lane == 31) wsum[w] = inc;
    __syncthreads();
    if (w == 0) {
        int v = wsum[lane];
        int s = v;
#pragma unroll
        for (int o = 1; o < 32; o <<= 1) {
            int x = __shfl_up_sync(0xffffffffu, s, o);
            if (lane >= o) s += x;
        }
        wsum[lane] = s - v;
    }
    __syncthreads();

    int run = wsum[w] + inc - sum;
    for (int i = lo; i < hi; i++) { rs[i] = run; run += deg[i]; }
    if (t == 1023) rs[NN] = run;
}

__global__ void csr_fill(const int* __restrict__ ei,
                         const int* __restrict__ rs,
                         int* __restrict__ cnt, int* __restrict__ csrc)
{
    int e = blockIdx.x * blockDim.x + threadIdx.x;
    if (e >= EE) return;
    int s, d;
    if (e < EDGES) { s = ei[e]; d = ei[EDGES + e]; }
    else           { s = d = e - EDGES; }
    int pos = rs[d] + atomicAdd(&cnt[d], 1);
    csrc[pos] = s;
}

// ---------------- register-tiled GEMM + fused attention-logit epilogue -------
// BM=64, BN=128, 256 threads, thread tile 4x8. hf written as fp16 (logits fp32).
__global__ __launch_bounds__(256) void gemm_attn(
    const float* __restrict__ fin, const float* __restrict__ W,
    const float* __restrict__ att_s, const float* __restrict__ att_d,
    uint2* __restrict__ hf, float* __restrict__ as_, float* __restrict__ ad_,
    int H)
{
    __shared__ float  Xs[64][33];
    __shared__ float4 Ws4[32 * 32];

    const int t    = threadIdx.x;
    const int lane = t & 31;
    const int tcol = t & 15;
    const int trow = t >> 4;
    const int row0 = blockIdx.x * 64;

    float acc[4][8];
#pragma unroll
    for (int i = 0; i < 4; i++)
#pragma unroll
        for (int j = 0; j < 8; j++) acc[i][j] = 0.f;

    for (int kc = 0; kc < 4; kc++) {
#pragma unroll
        for (int i = 0; i < 2; i++) {
            int idx = t + 256 * i;
            int r = idx >> 3, c = idx & 7;
            int gr = min(row0 + r, NN - 1);
            float4 v = *(const float4*)&fin[gr * F + kc * 32 + 4 * c];
            Xs[r][4 * c + 0] = v.x;
            Xs[r][4 * c + 1] = v.y;
            Xs[r][4 * c + 2] = v.z;
            Xs[r][4 * c + 3] = v.w;
        }
#pragma unroll
        for (int i = 0; i < 4; i++) {
            int idx = t + 256 * i;
            int k = idx >> 5, c = idx & 31;
            Ws4[k * 32 + c] = *(const float4*)&W[(kc * 32 + k) * F + 4 * c];
        }
        __syncthreads();

#pragma unroll
        for (int k = 0; k < 32; k++) {
            float a0 = Xs[trow * 4 + 0][k];
            float a1 = Xs[trow * 4 + 1][k];
            float a2 = Xs[trow * 4 + 2][k];
            float a3 = Xs[trow * 4 + 3][k];
            float4 b0 = Ws4[k * 32 + tcol];
            float4 b1 = Ws4[k * 32 + 16 + tcol];
            acc[0][0] += a0 * b0.x; acc[0][1] += a0 * b0.y;
            acc[0][2] += a0 * b0.z; acc[0][3] += a0 * b0.w;
            acc[0][4] += a0 * b1.x; acc[0][5] += a0 * b1.y;
            acc[0][6] += a0 * b1.z; acc[0][7] += a0 * b1.w;
            acc[1][0] += a1 * b0.x; acc[1][1] += a1 * b0.y;
            acc[1][2] += a1 * b0.z; acc[1][3] += a1 * b0.w;
            acc[1][4] += a1 * b1.x; acc[1][5] += a1 * b1.y;
            acc[1][6] += a1 * b1.z; acc[1][7] += a1 * b1.w;
            acc[2][0] += a2 * b0.x; acc[2][1] += a2 * b0.y;
            acc[2][2] += a2 * b0.z; acc[2][3] += a2 * b0.w;
            acc[2][4] += a2 * b1.x; acc[2][5] += a2 * b1.y;
            acc[2][6] += a2 * b1.z; acc[2][7] += a2 * b1.w;
            acc[3][0] += a3 * b0.x; acc[3][1] += a3 * b0.y;
            acc[3][2] += a3 * b0.z; acc[3][3] += a3 * b0.w;
            acc[3][4] += a3 * b1.x; acc[3][5] += a3 * b1.y;
            acc[3][6] += a3 * b1.z; acc[3][7] += a3 * b1.w;
        }
        __syncthreads();
    }

    const float4 sA = ((const float4*)att_s)[tcol];
    const float4 sB = ((const float4*)att_s)[16 + tcol];
    const float4 dA = ((const float4*)att_d)[tcol];
    const float4 dB = ((const float4*)att_d)[16 + tcol];

#pragma unroll
    for (int i = 0; i < 4; i++) {
        int gr = row0 + trow * 4 + i;
        bool ok = gr < NN;
        if (ok) {
            __half2 p0 = __floats2half2_rn(acc[i][0], acc[i][1]);
            __half2 p1 = __floats2half2_rn(acc[i][2], acc[i][3]);
            __half2 p2 = __floats2half2_rn(acc[i][4], acc[i][5]);
            __half2 p3 = __floats2half2_rn(acc[i][6], acc[i][7]);
            hf[gr * 32 + tcol]      = make_uint2(*(unsigned*)&p0, *(unsigned*)&p1);
            hf[gr * 32 + 16 + tcol] = make_uint2(*(unsigned*)&p2, *(unsigned*)&p3);
        }
        float psA = acc[i][0] * sA.x + acc[i][1] * sA.y + acc[i][2] * sA.z + acc[i][3] * sA.w;
        float psB = acc[i][4] * sB.x + acc[i][5] * sB.y + acc[i][6] * sB.z + acc[i][7] * sB.w;
        float pdA = acc[i][0] * dA.x + acc[i][1] * dA.y + acc[i][2] * dA.z + acc[i][3] * dA.w;
        float pdB = acc[i][4] * dB.x + acc[i][5] * dB.y + acc[i][6] * dB.z + acc[i][7] * dB.w;
        if (H == 4) {
#pragma unroll
            for (int o = 1; o < 8; o <<= 1) {
                psA += __shfl_xor_sync(0xffffffffu, psA, o);
                psB += __shfl_xor_sync(0xffffffffu, psB, o);
                pdA += __shfl_xor_sync(0xffffffffu, pdA, o);
                pdB += __shfl_xor_sync(0xffffffffu, pdB, o);
            }
            if ((lane & 7) == 0 && ok) {
                int h0 = (lane >> 3) & 1;
                as_[gr * 4 + h0]     = psA;
                as_[gr * 4 + h0 + 2] = psB;
                ad_[gr * 4 + h0]     = pdA;
                ad_[gr * 4 + h0 + 2] = pdB;
            }
        } else {
            float s = psA + psB, dd = pdA + pdB;
#pragma unroll
            for (int o = 1; o < 16; o <<= 1) {
                s  += __shfl_xor_sync(0xffffffffu, s,  o);
                dd += __shfl_xor_sync(0xffffffffu, dd, o);
            }
            if ((lane & 15) == 0 && ok) { as_[gr] = s; ad_[gr] = dd; }
        }
    }
}

// ---------------- fused softmax + aggregate: warp per dst node ----------------
// fp16 h gather (8B/lane/edge, coalesced 256B/edge), fp32 accumulate.
__global__ __launch_bounds__(256) void gat_gather(
    const int* __restrict__ rs, const int* __restrict__ csrc,
    const float* __restrict__ as_, const float* __restrict__ ad_,
    const uint2* __restrict__ hf, const float* __restrict__ b,
    float* __restrict__ out, int H, int elu)
{
    const int warp = (blockIdx.x * blockDim.x + threadIdx.x) >> 5;
    const int lane = threadIdx.x & 31;
    if (warp >= NN) return;
    const int d = warp;

    const int h = (H == 4) ? (lane >> 3) : 0;
    const float adv = ad_[d * H + h];

    float m = -CUDART_INF_F, den = 0.f;
    float4 acc = make_float4(0.f, 0.f, 0.f, 0.f);

    const int start = rs[d], end = rs[d + 1];
    const int gbase = lane & 24;

    for (int j = start; j < end; j += 32) {
        int sj = (j + lane < end) ? csrc[j + lane] : 0;
        int nb = min(32, end - j);
        for (int base = 0; base < nb; base += 8) {
            int nk = min(8, nb - base);
            int  s_my  = __shfl_sync(0xffffffffu, sj, base + (lane & 7));
            bool valid = (lane & 7) < nk;
            float v = -CUDART_INF_F;
            if (valid) {
                float vv = as_[s_my * H + h] + adv;
                v = vv > 0.f ? vv : 0.2f * vv;
            }
            float bm = v;
            bm = fmaxf(bm, __shfl_xor_sync(0xffffffffu, bm, 1));
            bm = fmaxf(bm, __shfl_xor_sync(0xffffffffu, bm, 2));
            bm = fmaxf(bm, __shfl_xor_sync(0xffffffffu, bm, 4));
            float mn = fmaxf(m, bm);
            float f  = __expf(m - mn);
            float p  = valid ? __expf(v - mn) : 0.f;
            float ps = p;
            ps += __shfl_xor_sync(0xffffffffu, ps, 1);
            ps += __shfl_xor_sync(0xffffffffu, ps, 2);
            ps += __shfl_xor_sync(0xffffffffu, ps, 4);
            den = den * f + ps;
            m = mn;
            acc.x *= f; acc.y *= f; acc.z *= f; acc.w *= f;
            for (int k = 0; k < nk; k++) {
                int   s  = __shfl_sync(0xffffffffu, sj, base + k);
                float pk = __shfl_sync(0xffffffffu, p, gbase + k);
                uint2 raw = hf[s * 32 + lane];
                float2 f01 = __half22float2(*(__half2*)&raw.x);
                float2 f23 = __half22float2(*(__half2*)&raw.y);
                acc.x += pk * f01.x;
                acc.y += pk * f01.y;
                acc.z += pk * f23.x;
                acc.w += pk * f23.y;
            }
        }
    }

    float inv = 1.f / den;
    const float4 bv = ((const float4*)b)[lane];
    float4 o;
    o.x = acc.x * inv + bv.x;
    o.y = acc.y * inv + bv.y;
    o.z = acc.z * inv + bv.z;
    o.w = acc.w * inv + bv.w;
    if (elu) {
        o.x = o.x > 0.f ? o.x : (__expf(o.x) - 1.f);
        o.y = o.y > 0.f ? o.y : (__expf(o.y) - 1.f);
        o.z = o.z > 0.f ? o.z : (__expf(o.z) - 1.f);
        o.w = o.w > 0.f ? o.w : (__expf(o.w) - 1.f);
    }
    ((float4*)out)[d * 32 + lane] = o;
}

// ---------------- host side ----------------
static void run_layer(const float* fin, const float* W, const float* ss,
                      const float* dd, const float* bb, int H, float* outp,
                      int elu, uint2* hf, float* as_, float* ad_,
                      const int* rs, const int* csrc)
{
    gemm_attn<<<(NN + 63) / 64, 256>>>(fin, W, ss, dd, hf, as_, ad_, H);
    gat_gather<<<(NN + 7) / 8, 256>>>(rs, csrc, as_, ad_, hf, bb, outp, H, elu);
}

extern "C" void kernel_launch(void* const* d_in, const int* in_sizes, int n_in,
                              void* d_out, int out_size)
{
    const float* x  = (const float*)d_in[0];
    const int*   ei = (const int*)d_in[1];
    const float* W1 = (const float*)d_in[2];
    const float* s1 = (const float*)d_in[3];
    const float* d1 = (const float*)d_in[4];
    const float* b1 = (const float*)d_in[5];
    const float* W2 = (const float*)d_in[6];
    const float* s2 = (const float*)d_in[7];
    const float* d2 = (const float*)d_in[8];
    const float* b2 = (const float*)d_in[9];
    const float* W3 = (const float*)d_in[10];
    const float* s3 = (const float*)d_in[11];
    const float* d3 = (const float*)d_in[12];
    const float* b3 = (const float*)d_in[13];

    uint2* hf;
    float *f0, *f1, *as_, *ad_;
    int *deg, *rs, *cnt, *csrc;
    cudaGetSymbolAddress((void**)&hf,   g_hf);
    cudaGetSymbolAddress((void**)&f0,   g_f0);
    cudaGetSymbolAddress((void**)&f1,   g_f1);
    cudaGetSymbolAddress((void**)&as_,  g_as);
    cudaGetSymbolAddress((void**)&ad_,  g_ad);
    cudaGetSymbolAddress((void**)&deg,  g_deg);
    cudaGetSymbolAddress((void**)&rs,   g_rs);
    cudaGetSymbolAddress((void**)&cnt,  g_cnt);
    cudaGetSymbolAddress((void**)&csrc, g_src);

    cudaMemsetAsync(deg, 0, NN * sizeof(int));
    cudaMemsetAsync(cnt, 0, NN * sizeof(int));
    const int blk = 256;
    csr_hist<<<(EE + blk - 1) / blk, blk>>>(ei, deg);
    csr_scan<<<1, 1024>>>(deg, rs);
    csr_fill<<<(EE + blk - 1) / blk, blk>>>(ei, rs, cnt, csrc);

    run_layer(x,  W1, s1, d1, b1, 4, f0,            1, hf, as_, ad_, rs, csrc);
    run_layer(f0, W2, s2, d2, b2, 4, f1,            1, hf, as_, ad_, rs, csrc);
    run_layer(f1, W3, s3, d3, b3, 1, (float*)d_out, 0, hf, as_, ad_, rs, csrc);
}